// round 4
// baseline (speedup 1.0000x reference)
#include <cuda_runtime.h>

// Swin attention layer, fused per-window, fp32 SIMT baseline.
// M=32, H=W=64, D=256, 8x8 windows (ws=64 tokens), 8 heads (hd=32), shift=4.

#define IMG_M 32
#define IMG_H 64
#define IMG_W 64
#define DIM   256
#define NHEAD 8
#define HDIM  32
#define NWIN  64     // windows per image (8x8)

#define STRIDE 268   // padded row stride (floats) for token-major smem buffers
#define SSTR   68    // padded row stride for scores

#define SM_A 0
#define SM_K (64*STRIDE)
#define SM_V (2*64*STRIDE)
#define SM_T (3*64*STRIDE)
#define SM_FLOATS (3*64*STRIDE + 64*SSTR)   // 55808 floats = 223232 B

// inter-pass intermediate (static scratch: allocation-free rule)
__device__ float g_y[IMG_M*IMG_H*IMG_W*DIM];

__device__ __forceinline__ int regid(int wh, int ww, int t) {
    int r = t >> 3, c = t & 7;
    int hr = (wh == 7) ? ((r < 4) ? 1 : 2) : 0;
    int wr = (ww == 7) ? ((c < 4) ? 1 : 2) : 0;
    return hr * 3 + wr;
}

// C[64][256] = As[64][256] @ Wg[:, colbase:colbase+256] + bias
// thread tile: 8 rows (ty) x 8 cols (tx: cols {tx*4+j} and {128+tx*4+j})
__device__ __forceinline__ void gemm_64x256(
    const float* __restrict__ As, float* __restrict__ Ts,
    const float* __restrict__ Wg, int ldw, int colbase,
    const float* __restrict__ bias, float acc[8][8], int tid)
{
    const int ty = tid >> 5, tx = tid & 31;
#pragma unroll
    for (int i = 0; i < 8; ++i)
#pragma unroll
        for (int j = 0; j < 8; ++j) acc[i][j] = 0.f;

    for (int k0 = 0; k0 < 256; k0 += 16) {
        // stage W tile [16][256] into Ts (coalesced float4)
#pragma unroll
        for (int s = 0; s < 4; ++s) {
            int f4 = tid + s * 256;           // 0..1023
            int row = f4 >> 6, c4 = f4 & 63;
            *(float4*)(Ts + row * 256 + c4 * 4) =
                *(const float4*)(Wg + (k0 + row) * ldw + colbase + c4 * 4);
        }
        __syncthreads();
#pragma unroll
        for (int kk = 0; kk < 16; kk += 4) {
            float4 a4[8];
#pragma unroll
            for (int i = 0; i < 8; ++i)
                a4[i] = *(const float4*)(As + (ty * 8 + i) * STRIDE + k0 + kk);
#pragma unroll
            for (int u = 0; u < 4; ++u) {
                float4 b0 = *(const float4*)(Ts + (kk + u) * 256 + tx * 4);
                float4 b1 = *(const float4*)(Ts + (kk + u) * 256 + 128 + tx * 4);
#pragma unroll
                for (int i = 0; i < 8; ++i) {
                    float av = (u == 0) ? a4[i].x : (u == 1) ? a4[i].y
                             : (u == 2) ? a4[i].z : a4[i].w;
                    acc[i][0] = fmaf(av, b0.x, acc[i][0]);
                    acc[i][1] = fmaf(av, b0.y, acc[i][1]);
                    acc[i][2] = fmaf(av, b0.z, acc[i][2]);
                    acc[i][3] = fmaf(av, b0.w, acc[i][3]);
                    acc[i][4] = fmaf(av, b1.x, acc[i][4]);
                    acc[i][5] = fmaf(av, b1.y, acc[i][5]);
                    acc[i][6] = fmaf(av, b1.z, acc[i][6]);
                    acc[i][7] = fmaf(av, b1.w, acc[i][7]);
                }
            }
        }
        __syncthreads();
    }
    float4 c0 = *(const float4*)(bias + colbase + tx * 4);
    float4 c1 = *(const float4*)(bias + colbase + 128 + tx * 4);
#pragma unroll
    for (int i = 0; i < 8; ++i) {
        acc[i][0] += c0.x; acc[i][1] += c0.y; acc[i][2] += c0.z; acc[i][3] += c0.w;
        acc[i][4] += c1.x; acc[i][5] += c1.y; acc[i][6] += c1.z; acc[i][7] += c1.w;
    }
}

__global__ __launch_bounds__(256, 1)
void swin_pass_kernel(const float* __restrict__ xin,
                      const float* __restrict__ wqkv,
                      const float* __restrict__ bqkv,
                      const float* __restrict__ wo,
                      const float* __restrict__ bo,
                      float* __restrict__ yout,
                      int shifted)
{
    extern __shared__ float sm[];
    float* A  = sm + SM_A;   // x -> q -> attn_out
    float* Kb = sm + SM_K;
    float* Vb = sm + SM_V;
    float* Ts = sm + SM_T;   // W tiles / scores

    const int tid = threadIdx.x;
    const int blk = blockIdx.x;
    const int m  = blk >> 6;
    const int w  = blk & 63;
    const int wh = w >> 3, ww = w & 7;

    const float* srcimg = shifted ? g_y : xin;
    float*       dstimg = shifted ? yout : g_y;

    // ---- phase 0: gather window (with roll for shifted pass) ----
#pragma unroll
    for (int it = 0; it < 16; ++it) {
        int f4 = tid + it * 256;           // 0..4095
        int t  = f4 >> 6;                  // token 0..63
        int c4 = f4 & 63;                  // float4 within token
        int r = t >> 3, c = t & 7;
        int gh = wh * 8 + r, gw = ww * 8 + c;
        if (shifted) { gh = (gh + 4) & 63; gw = (gw + 4) & 63; }
        float4 val = *(const float4*)(srcimg + ((m * IMG_H + gh) * IMG_W + gw) * DIM + c4 * 4);
        *(float4*)(A + t * STRIDE + c4 * 4) = val;
    }
    __syncthreads();

    const int ty = tid >> 5, tx = tid & 31;
    float acc[8][8];

    // ---- phase 1: QKV projections ----
    // K
    gemm_64x256(A, Ts, wqkv, 3 * DIM, 256, bqkv, acc, tid);
#pragma unroll
    for (int i = 0; i < 8; ++i) {
        *(float4*)(Kb + (ty * 8 + i) * STRIDE + tx * 4) =
            make_float4(acc[i][0], acc[i][1], acc[i][2], acc[i][3]);
        *(float4*)(Kb + (ty * 8 + i) * STRIDE + 128 + tx * 4) =
            make_float4(acc[i][4], acc[i][5], acc[i][6], acc[i][7]);
    }
    // V
    gemm_64x256(A, Ts, wqkv, 3 * DIM, 512, bqkv, acc, tid);
#pragma unroll
    for (int i = 0; i < 8; ++i) {
        *(float4*)(Vb + (ty * 8 + i) * STRIDE + tx * 4) =
            make_float4(acc[i][0], acc[i][1], acc[i][2], acc[i][3]);
        *(float4*)(Vb + (ty * 8 + i) * STRIDE + 128 + tx * 4) =
            make_float4(acc[i][4], acc[i][5], acc[i][6], acc[i][7]);
    }
    // Q (overwrites A; final internal sync of gemm guarantees all A reads done)
    gemm_64x256(A, Ts, wqkv, 3 * DIM, 0, bqkv, acc, tid);
#pragma unroll
    for (int i = 0; i < 8; ++i) {
        *(float4*)(A + (ty * 8 + i) * STRIDE + tx * 4) =
            make_float4(acc[i][0], acc[i][1], acc[i][2], acc[i][3]);
        *(float4*)(A + (ty * 8 + i) * STRIDE + 128 + tx * 4) =
            make_float4(acc[i][4], acc[i][5], acc[i][6], acc[i][7]);
    }
    __syncthreads();

    // ---- phase 2: per-head attention ----
    const float scale = 0.17677669529663687f;  // 1/sqrt(32)
    const int sy = tid >> 4, sx = tid & 15;    // scores: 4x4 per thread
    const int ry = tid >> 3, rx = tid & 7;     // attn@v: 2 rows x 4 cols per thread

    for (int h = 0; h < NHEAD; ++h) {
        // scores = q_h @ k_h^T
        float sacc[4][4];
#pragma unroll
        for (int i = 0; i < 4; ++i)
#pragma unroll
            for (int j = 0; j < 4; ++j) sacc[i][j] = 0.f;
#pragma unroll
        for (int d4 = 0; d4 < 8; ++d4) {
            float4 qa[4], kb[4];
#pragma unroll
            for (int i = 0; i < 4; ++i)
                qa[i] = *(const float4*)(A + (sy * 4 + i) * STRIDE + h * HDIM + d4 * 4);
#pragma unroll
            for (int j = 0; j < 4; ++j)
                kb[j] = *(const float4*)(Kb + (sx * 4 + j) * STRIDE + h * HDIM + d4 * 4);
#pragma unroll
            for (int i = 0; i < 4; ++i)
#pragma unroll
                for (int j = 0; j < 4; ++j) {
                    sacc[i][j] = fmaf(qa[i].x, kb[j].x, sacc[i][j]);
                    sacc[i][j] = fmaf(qa[i].y, kb[j].y, sacc[i][j]);
                    sacc[i][j] = fmaf(qa[i].z, kb[j].z, sacc[i][j]);
                    sacc[i][j] = fmaf(qa[i].w, kb[j].w, sacc[i][j]);
                }
        }
        __syncthreads();   // previous head's reads of Ts (attn weights) are done

        // scale + swin mask, write scores
#pragma unroll
        for (int i = 0; i < 4; ++i) {
            int tiq = sy * 4 + i;
            float4 v;
            v.x = sacc[i][0] * scale; v.y = sacc[i][1] * scale;
            v.z = sacc[i][2] * scale; v.w = sacc[i][3] * scale;
            if (shifted) {
                int ri = regid(wh, ww, tiq);
                if (regid(wh, ww, sx * 4 + 0) != ri) v.x += -1e9f;
                if (regid(wh, ww, sx * 4 + 1) != ri) v.y += -1e9f;
                if (regid(wh, ww, sx * 4 + 2) != ri) v.z += -1e9f;
                if (regid(wh, ww, sx * 4 + 3) != ri) v.w += -1e9f;
            }
            *(float4*)(Ts + tiq * SSTR + sx * 4) = v;
        }
        __syncthreads();

        // softmax: 4 threads per row, 16 cols each; combine via quad shuffles
        {
            int row = tid >> 2, part = tid & 3;
            float* srow = Ts + row * SSTR + part * 16;
            float vals[16];
            float mx = -3.4e38f;
#pragma unroll
            for (int u = 0; u < 16; ++u) { vals[u] = srow[u]; mx = fmaxf(mx, vals[u]); }
            mx = fmaxf(mx, __shfl_xor_sync(0xffffffffu, mx, 1));
            mx = fmaxf(mx, __shfl_xor_sync(0xffffffffu, mx, 2));
            float s = 0.f;
#pragma unroll
            for (int u = 0; u < 16; ++u) { vals[u] = __expf(vals[u] - mx); s += vals[u]; }
            s += __shfl_xor_sync(0xffffffffu, s, 1);
            s += __shfl_xor_sync(0xffffffffu, s, 2);
            float inv = 1.f / s;
#pragma unroll
            for (int u = 0; u < 16; ++u) srow[u] = vals[u] * inv;
        }
        __syncthreads();

        // out_h = attn @ v_h, overwrite A[:, h*32 : h*32+32]
        float oacc[2][4];
#pragma unroll
        for (int i = 0; i < 2; ++i)
#pragma unroll
            for (int jj = 0; jj < 4; ++jj) oacc[i][jj] = 0.f;
#pragma unroll 4
        for (int j = 0; j < 64; ++j) {
            float4 bv = *(const float4*)(Vb + j * STRIDE + h * HDIM + rx * 4);
#pragma unroll
            for (int i = 0; i < 2; ++i) {
                float av = Ts[(ry * 2 + i) * SSTR + j];
                oacc[i][0] = fmaf(av, bv.x, oacc[i][0]);
                oacc[i][1] = fmaf(av, bv.y, oacc[i][1]);
                oacc[i][2] = fmaf(av, bv.z, oacc[i][2]);
                oacc[i][3] = fmaf(av, bv.w, oacc[i][3]);
            }
        }
#pragma unroll
        for (int i = 0; i < 2; ++i)
            *(float4*)(A + (ry * 2 + i) * STRIDE + h * HDIM + rx * 4) =
                make_float4(oacc[i][0], oacc[i][1], oacc[i][2], oacc[i][3]);
    }
    __syncthreads();   // attn_out complete + last head's Ts reads done

    // ---- phase 3: output projection + scatter store ----
    gemm_64x256(A, Ts, wo, DIM, 0, bo, acc, tid);
#pragma unroll
    for (int i = 0; i < 8; ++i) {
        int t = ty * 8 + i;
        int r = t >> 3, c = t & 7;
        int gh = wh * 8 + r, gw = ww * 8 + c;
        if (shifted) { gh = (gh + 4) & 63; gw = (gw + 4) & 63; }
        float* o = dstimg + ((m * IMG_H + gh) * IMG_W + gw) * DIM;
        *(float4*)(o + tx * 4) = make_float4(acc[i][0], acc[i][1], acc[i][2], acc[i][3]);
        *(float4*)(o + 128 + tx * 4) = make_float4(acc[i][4], acc[i][5], acc[i][6], acc[i][7]);
    }
}

extern "C" void kernel_launch(void* const* d_in, const int* in_sizes, int n_in,
                              void* d_out, int out_size) {
    (void)in_sizes; (void)n_in; (void)out_size;
    const float* x    = (const float*)d_in[0];
    const float* wqkv = (const float*)d_in[1];
    const float* bqkv = (const float*)d_in[2];
    const float* wo   = (const float*)d_in[3];
    const float* bo   = (const float*)d_in[4];
    float* out = (float*)d_out;

    cudaFuncSetAttribute(swin_pass_kernel,
                         cudaFuncAttributeMaxDynamicSharedMemorySize, SM_FLOATS * 4);

    dim3 grid(IMG_M * NWIN);
    swin_pass_kernel<<<grid, 256, SM_FLOATS * 4>>>(x, wqkv, bqkv, wo, bo, out, 0);
    swin_pass_kernel<<<grid, 256, SM_FLOATS * 4>>>(x, wqkv, bqkv, wo, bo, out, 1);
}

// round 6
// speedup vs baseline: 1.6167x; 1.6167x over previous
#include <cuda_runtime.h>
#include <cuda_bf16.h>
#include <cstdint>

// Swin layer: HMMA (mma.sync bf16 hi/lo split) GEMMs + SIMT fp32 attention.
#define NTOK 131072          // 32 * 64 * 64 tokens

// -------- device scratch (allocation-free rule) --------
__device__ float g_y  [NTOK * 256];
__device__ float g_qkv[(size_t)NTOK * 768];
__device__ float g_att[NTOK * 256];
__device__ __nv_bfloat16 g_wtq_hi[768 * 256];   // W_qkv^T  [N][K]
__device__ __nv_bfloat16 g_wtq_lo[768 * 256];
__device__ __nv_bfloat16 g_wto_hi[256 * 256];   // W_o^T    [N][K]
__device__ __nv_bfloat16 g_wto_lo[256 * 256];

// ======================= helpers =======================
__device__ __forceinline__ uint32_t smem_u32(const void* p) {
    uint32_t a;
    asm("{ .reg .u64 t; cvta.to.shared.u64 t, %1; cvt.u32.u64 %0, t; }" : "=r"(a) : "l"(p));
    return a;
}
__device__ __forceinline__ void ldsm4(uint32_t r[4], uint32_t addr) {
    asm volatile("ldmatrix.sync.aligned.m8n8.x4.shared.b16 {%0,%1,%2,%3}, [%4];"
                 : "=r"(r[0]), "=r"(r[1]), "=r"(r[2]), "=r"(r[3]) : "r"(addr));
}
__device__ __forceinline__ void mma16816(float d[4], const uint32_t a[4],
                                         uint32_t b0, uint32_t b1) {
    asm volatile(
        "mma.sync.aligned.m16n8k16.row.col.f32.bf16.bf16.f32 "
        "{%0,%1,%2,%3}, {%4,%5,%6,%7}, {%8,%9}, {%0,%1,%2,%3};"
        : "+f"(d[0]), "+f"(d[1]), "+f"(d[2]), "+f"(d[3])
        : "r"(a[0]), "r"(a[1]), "r"(a[2]), "r"(a[3]), "r"(b0), "r"(b1));
}

// ======================= prep: W^T hi/lo split =======================
__global__ void prep_kernel(const float* __restrict__ wqkv, const float* __restrict__ wo) {
    int i = blockIdx.x * blockDim.x + threadIdx.x;
    if (i < 768 * 256) {
        int n = i >> 8, k = i & 255;
        float f = wqkv[k * 768 + n];
        __nv_bfloat16 h = __float2bfloat16(f);
        g_wtq_hi[i] = h;
        g_wtq_lo[i] = __float2bfloat16(f - __bfloat162float(h));
    } else if (i < 768 * 256 + 256 * 256) {
        int j = i - 768 * 256;
        int n = j >> 8, k = j & 255;
        float f = wo[k * 256 + n];
        __nv_bfloat16 h = __float2bfloat16(f);
        g_wto_hi[j] = h;
        g_wto_lo[j] = __float2bfloat16(f - __bfloat162float(h));
    }
}

// ======================= HMMA GEMM kernel =======================
// out[tok, nt*128+c] = A[tok, 0:256] @ W^T rows + bias.
// A smem: bf16 [128][256], padded stride 264 elems; hi then lo.
// B smem: per 64-K chunk, [128 n][64 k] stride 72 elems; hi+lo, double-buffered.
#define LDA      264
#define A_LO_OFF 67584                    // 128*264*2
#define GB_OFF   135168                   // 2*67584
#define B_BUF    36864                    // (hi+lo) per buffer
#define B_HALF   18432                    // 128*72*2
#define LDB_B    144                      // 72 elems * 2 bytes
#define GS_SMEM  (GB_OFF + 2 * B_BUF)     // 208896 B

__global__ __launch_bounds__(256, 1)
void gemm_hmma(const float* __restrict__ lin_in, const float* __restrict__ img_in,
               const __nv_bfloat16* __restrict__ wh, const __nv_bfloat16* __restrict__ wl,
               const float* __restrict__ bias,
               float* __restrict__ lin_out, float* __restrict__ img_out,
               int ntiles, int out_stride, int mode_in, int mode_out, int shifted)
{
    extern __shared__ char sb[];
    const uint32_t smb = smem_u32(sb);
    const int tid = threadIdx.x, wid = tid >> 5, lane = tid & 31;
    const int blk = blockIdx.x;
    const int sh = shifted ? 4 : 0;

    // ---- load A (128 rows x 256 fp32), split to bf16 hi/lo ----
    for (int g = tid; g < 4096; g += 256) {
        int t = g >> 5;                 // row 0..127
        int col0 = (g & 31) * 8;        // 0..248
        const float* sp;
        if (mode_in == 1) {
            int tok = blk * 128 + t;
            int m = tok >> 12, w = (tok >> 6) & 63, tt = tok & 63;
            int gh = ((w >> 3) * 8 + (tt >> 3) + sh) & 63;
            int gw = ((w & 7) * 8 + (tt & 7) + sh) & 63;
            sp = img_in + (size_t)((m * 64 + gh) * 64 + gw) * 256 + col0;
        } else {
            sp = lin_in + (size_t)(blk * 128 + t) * 256 + col0;
        }
        float4 f0 = *(const float4*)sp, f1 = *(const float4*)(sp + 4);
        float fv[8] = {f0.x, f0.y, f0.z, f0.w, f1.x, f1.y, f1.z, f1.w};
        uint32_t hw[4], lw[4];
#pragma unroll
        for (int q = 0; q < 4; ++q) {
            __nv_bfloat16 h0 = __float2bfloat16(fv[2 * q]);
            __nv_bfloat16 h1 = __float2bfloat16(fv[2 * q + 1]);
            __nv_bfloat16 l0 = __float2bfloat16(fv[2 * q]     - __bfloat162float(h0));
            __nv_bfloat16 l1 = __float2bfloat16(fv[2 * q + 1] - __bfloat162float(h1));
            hw[q] = (uint32_t)__bfloat16_as_ushort(h0) | ((uint32_t)__bfloat16_as_ushort(h1) << 16);
            lw[q] = (uint32_t)__bfloat16_as_ushort(l0) | ((uint32_t)__bfloat16_as_ushort(l1) << 16);
        }
        uint32_t off = ((uint32_t)t * LDA + col0) * 2;
        *(uint4*)(sb + off)            = make_uint4(hw[0], hw[1], hw[2], hw[3]);
        *(uint4*)(sb + A_LO_OFF + off) = make_uint4(lw[0], lw[1], lw[2], lw[3]);
    }

    // per-thread ldmatrix lane addressing
    const int mbase = (wid & 3) * 32;
    const int nbase = (wid >> 2) * 64;
    const int grp = lane >> 3, r8 = lane & 7;
    const int a_row = mbase + r8 + ((grp & 1) << 3);
    const int a_kof = (grp & 2) ? 8 : 0;
    const uint32_t aHi = smb + (uint32_t)(a_row * LDA + a_kof) * 2;
    const uint32_t aLo = aHi + A_LO_OFF;
    const int b_n  = r8 + ((grp & 2) << 2);
    const int b_kof = (grp & 1) ? 8 : 0;
    const uint32_t bBase = smb + GB_OFF + (uint32_t)((nbase + b_n) * 72 + b_kof) * 2;

    const int qr = lane >> 2, qc = (lane & 3) * 2;

    for (int nt = 0; nt < ntiles; ++nt) {
        float d[2][8][4];
#pragma unroll
        for (int mf = 0; mf < 2; ++mf)
#pragma unroll
            for (int nf = 0; nf < 8; ++nf)
#pragma unroll
                for (int q = 0; q < 4; ++q) d[mf][nf][q] = 0.f;

        // stage chunk 0 into buffer 0
#pragma unroll
        for (int i = 0; i < 8; ++i) {
            int g = tid + i * 256;
            int half = g >> 10, j = g & 1023;
            int n = j >> 3, kq = j & 7;
            const __nv_bfloat16* W = half ? wl : wh;
            uint4 v = *(const uint4*)(W + (size_t)(nt * 128 + n) * 256 + kq * 8);
            *(uint4*)(sb + GB_OFF + half * B_HALF + n * LDB_B + kq * 16) = v;
        }
        __syncthreads();

        for (int c = 0; c < 4; ++c) {
            uint4 stg[8];
            if (c < 3) {   // prefetch next chunk into registers
#pragma unroll
                for (int i = 0; i < 8; ++i) {
                    int g = tid + i * 256;
                    int half = g >> 10, j = g & 1023;
                    int n = j >> 3, kq = j & 7;
                    const __nv_bfloat16* W = half ? wl : wh;
                    stg[i] = *(const uint4*)(W + (size_t)(nt * 128 + n) * 256 + (c + 1) * 64 + kq * 8);
                }
            }
            const uint32_t bb0 = bBase + (uint32_t)(c & 1) * B_BUF;

#pragma unroll
            for (int kk8 = 0; kk8 < 4; ++kk8) {
                const int kg = c * 64 + kk8 * 16;
                uint32_t ah[2][4], al[2][4];
                ldsm4(ah[0], aHi + (uint32_t)kg * 2);
                ldsm4(ah[1], aHi + 16u * (LDA * 2) + (uint32_t)kg * 2);
                ldsm4(al[0], aLo + (uint32_t)kg * 2);
                ldsm4(al[1], aLo + 16u * (LDA * 2) + (uint32_t)kg * 2);
                uint32_t bh[4][4], bl[4][4];
                const uint32_t bb = bb0 + (uint32_t)kk8 * 32;
#pragma unroll
                for (int np = 0; np < 4; ++np) {
                    ldsm4(bh[np], bb + (uint32_t)np * (16 * LDB_B));
                    ldsm4(bl[np], bb + B_HALF + (uint32_t)np * (16 * LDB_B));
                }
#pragma unroll
                for (int mf = 0; mf < 2; ++mf)
#pragma unroll
                    for (int nf = 0; nf < 8; ++nf) {
                        const int np = nf >> 1, hv = (nf & 1) * 2;
                        mma16816(d[mf][nf], ah[mf], bh[np][hv], bh[np][hv + 1]);
                        mma16816(d[mf][nf], ah[mf], bl[np][hv], bl[np][hv + 1]);
                        mma16816(d[mf][nf], al[mf], bh[np][hv], bh[np][hv + 1]);
                    }
            }
            if (c < 3) {
#pragma unroll
                for (int i = 0; i < 8; ++i) {
                    int g = tid + i * 256;
                    int half = g >> 10, j = g & 1023;
                    int n = j >> 3, kq = j & 7;
                    *(uint4*)(sb + GB_OFF + ((c + 1) & 1) * B_BUF + half * B_HALF + n * LDB_B + kq * 16) = stg[i];
                }
            }
            __syncthreads();
        }

        // ---- epilogue: bias + store ----
#pragma unroll
        for (int mf = 0; mf < 2; ++mf)
#pragma unroll
            for (int h8 = 0; h8 < 2; ++h8) {
                int row = mbase + mf * 16 + h8 * 8 + qr;
                int tok = blk * 128 + row;
                float* dst;
                if (mode_out == 0) {
                    dst = lin_out + (size_t)tok * out_stride + nt * 128;
                } else {
                    int m = tok >> 12, w = (tok >> 6) & 63, tt = tok & 63;
                    int gh = ((w >> 3) * 8 + (tt >> 3) + sh) & 63;
                    int gw = ((w & 7) * 8 + (tt & 7) + sh) & 63;
                    dst = img_out + (size_t)((m * 64 + gh) * 64 + gw) * 256 + nt * 128;
                }
#pragma unroll
                for (int nf = 0; nf < 8; ++nf) {
                    int col = nbase + nf * 8 + qc;
                    float b0 = bias[nt * 128 + col], b1 = bias[nt * 128 + col + 1];
                    *(float2*)(dst + col) = make_float2(d[mf][nf][h8 * 2] + b0,
                                                        d[mf][nf][h8 * 2 + 1] + b1);
                }
            }
    }
}

// ======================= SIMT attention kernel =======================
#define STRIDE 268
#define SSTR   68
#define AT_A 0
#define AT_K (64 * STRIDE)
#define AT_V (2 * 64 * STRIDE)
#define AT_S (3 * 64 * STRIDE)
#define AT_FLOATS (3 * 64 * STRIDE + 64 * SSTR)   // 223232 B

__device__ __forceinline__ int regid(int wh, int ww, int t) {
    int r = t >> 3, c = t & 7;
    int hr = (wh == 7) ? ((r < 4) ? 1 : 2) : 0;
    int wr = (ww == 7) ? ((c < 4) ? 1 : 2) : 0;
    return hr * 3 + wr;
}

__global__ __launch_bounds__(256, 1)
void attn_kernel(int shifted)
{
    extern __shared__ float smf[];
    float* A  = smf + AT_A;
    float* Kb = smf + AT_K;
    float* Vb = smf + AT_V;
    float* Ts = smf + AT_S;

    const int tid = threadIdx.x;
    const int win = blockIdx.x;
    const int wh = (win & 63) >> 3, ww = win & 7;

#pragma unroll
    for (int it = 0; it < 16; ++it) {
        int f4 = tid + it * 256;
        int t = f4 >> 6, c4 = f4 & 63;
        const float* base = g_qkv + (size_t)(win * 64 + t) * 768 + c4 * 4;
        *(float4*)(A  + t * STRIDE + c4 * 4) = *(const float4*)(base);
        *(float4*)(Kb + t * STRIDE + c4 * 4) = *(const float4*)(base + 256);
        *(float4*)(Vb + t * STRIDE + c4 * 4) = *(const float4*)(base + 512);
    }
    __syncthreads();

    const float scale = 0.17677669529663687f;
    const int sy = tid >> 4, sx = tid & 15;
    const int ry = tid >> 3, rx = tid & 7;

    for (int h = 0; h < 8; ++h) {
        float sacc[4][4];
#pragma unroll
        for (int i = 0; i < 4; ++i)
#pragma unroll
            for (int j = 0; j < 4; ++j) sacc[i][j] = 0.f;
#pragma unroll
        for (int d4 = 0; d4 < 8; ++d4) {
            float4 qa[4], kb[4];
#pragma unroll
            for (int i = 0; i < 4; ++i)
                qa[i] = *(const float4*)(A + (sy * 4 + i) * STRIDE + h * 32 + d4 * 4);
#pragma unroll
            for (int j = 0; j < 4; ++j)
                kb[j] = *(const float4*)(Kb + (sx * 4 + j) * STRIDE + h * 32 + d4 * 4);
#pragma unroll
            for (int i = 0; i < 4; ++i)
#pragma unroll
                for (int j = 0; j < 4; ++j) {
                    sacc[i][j] = fmaf(qa[i].x, kb[j].x, sacc[i][j]);
                    sacc[i][j] = fmaf(qa[i].y, kb[j].y, sacc[i][j]);
                    sacc[i][j] = fmaf(qa[i].z, kb[j].z, sacc[i][j]);
                    sacc[i][j] = fmaf(qa[i].w, kb[j].w, sacc[i][j]);
                }
        }
        __syncthreads();

#pragma unroll
        for (int i = 0; i < 4; ++i) {
            int tiq = sy * 4 + i;
            float4 v;
            v.x = sacc[i][0] * scale; v.y = sacc[i][1] * scale;
            v.z = sacc[i][2] * scale; v.w = sacc[i][3] * scale;
            if (shifted) {
                int ri = regid(wh, ww, tiq);
                if (regid(wh, ww, sx * 4 + 0) != ri) v.x += -1e9f;
                if (regid(wh, ww, sx * 4 + 1) != ri) v.y += -1e9f;
                if (regid(wh, ww, sx * 4 + 2) != ri) v.z += -1e9f;
                if (regid(wh, ww, sx * 4 + 3) != ri) v.w += -1e9f;
            }
            *(float4*)(Ts + tiq * SSTR + sx * 4) = v;
        }
        __syncthreads();

        {   // softmax: 4 threads per row
            int row = tid >> 2, part = tid & 3;
            float* srow = Ts + row * SSTR + part * 16;
            float vals[16];
            float mx = -3.4e38f;
#pragma unroll
            for (int u = 0; u < 16; ++u) { vals[u] = srow[u]; mx = fmaxf(mx, vals[u]); }
            mx = fmaxf(mx, __shfl_xor_sync(0xffffffffu, mx, 1));
            mx = fmaxf(mx, __shfl_xor_sync(0xffffffffu, mx, 2));
            float s = 0.f;
#pragma unroll
            for (int u = 0; u < 16; ++u) { vals[u] = __expf(vals[u] - mx); s += vals[u]; }
            s += __shfl_xor_sync(0xffffffffu, s, 1);
            s += __shfl_xor_sync(0xffffffffu, s, 2);
            float inv = 1.f / s;
#pragma unroll
            for (int u = 0; u < 16; ++u) srow[u] = vals[u] * inv;
        }
        __syncthreads();

        float oacc[2][4];
#pragma unroll
        for (int i = 0; i < 2; ++i)
#pragma unroll
            for (int jj = 0; jj < 4; ++jj) oacc[i][jj] = 0.f;
#pragma unroll 4
        for (int j = 0; j < 64; ++j) {
            float4 bv = *(const float4*)(Vb + j * STRIDE + h * 32 + rx * 4);
#pragma unroll
            for (int i = 0; i < 2; ++i) {
                float av = Ts[(ry * 2 + i) * SSTR + j];
                oacc[i][0] = fmaf(av, bv.x, oacc[i][0]);
                oacc[i][1] = fmaf(av, bv.y, oacc[i][1]);
                oacc[i][2] = fmaf(av, bv.z, oacc[i][2]);
                oacc[i][3] = fmaf(av, bv.w, oacc[i][3]);
            }
        }
#pragma unroll
        for (int i = 0; i < 2; ++i)
            *(float4*)(A + (ry * 2 + i) * STRIDE + h * 32 + rx * 4) =
                make_float4(oacc[i][0], oacc[i][1], oacc[i][2], oacc[i][3]);
    }
    __syncthreads();

#pragma unroll
    for (int it = 0; it < 16; ++it) {
        int f4 = tid + it * 256;
        int t = f4 >> 6, c4 = f4 & 63;
        *(float4*)(g_att + (size_t)(win * 64 + t) * 256 + c4 * 4) =
            *(const float4*)(A + t * STRIDE + c4 * 4);
    }
}

// ======================= launch =======================
extern "C" void kernel_launch(void* const* d_in, const int* in_sizes, int n_in,
                              void* d_out, int out_size) {
    (void)in_sizes; (void)n_in; (void)out_size;
    const float* x    = (const float*)d_in[0];
    const float* wqkv = (const float*)d_in[1];
    const float* bqkv = (const float*)d_in[2];
    const float* wo   = (const float*)d_in[3];
    const float* bo   = (const float*)d_in[4];
    float* out = (float*)d_out;

    cudaFuncSetAttribute(gemm_hmma,  cudaFuncAttributeMaxDynamicSharedMemorySize, GS_SMEM);
    cudaFuncSetAttribute(attn_kernel, cudaFuncAttributeMaxDynamicSharedMemorySize, AT_FLOATS * 4);

    float* ypass1; cudaGetSymbolAddress((void**)&ypass1, g_y);
    __nv_bfloat16 *wqh, *wql, *woh, *wol;
    cudaGetSymbolAddress((void**)&wqh, g_wtq_hi);
    cudaGetSymbolAddress((void**)&wql, g_wtq_lo);
    cudaGetSymbolAddress((void**)&woh, g_wto_hi);
    cudaGetSymbolAddress((void**)&wol, g_wto_lo);
    float *qkvp, *attp;
    cudaGetSymbolAddress((void**)&qkvp, g_qkv);
    cudaGetSymbolAddress((void**)&attp, g_att);

    prep_kernel<<<1024, 256>>>(wqkv, wo);

    for (int pass = 0; pass < 2; ++pass) {
        const float* img = pass ? (const float*)ypass1 : x;
        float* oimg = pass ? out : ypass1;
        // QKV: gather windows (+roll) -> g_qkv [tok, 768]
        gemm_hmma<<<1024, 256, GS_SMEM>>>(nullptr, img, wqh, wql, bqkv,
                                          qkvp, nullptr, 6, 768, 1, 0, pass);
        // attention per window
        attn_kernel<<<2048, 256, AT_FLOATS * 4>>>(pass);
        // O-projection: linear in -> scatter out (+roll back)
        gemm_hmma<<<1024, 256, GS_SMEM>>>(attp, nullptr, woh, wol, bo,
                                          nullptr, oimg, 2, 256, 0, 1, pass);
    }
}

// round 7
// speedup vs baseline: 2.2974x; 1.4210x over previous
#include <cuda_runtime.h>
#include <cuda_bf16.h>
#include <cstdint>

// Swin layer: HMMA (mma.sync bf16 hi/lo split) GEMMs + HMMA flash attention.
#define NTOK 131072          // 32 * 64 * 64 tokens

// -------- device scratch (allocation-free rule) --------
__device__ float g_y  [NTOK * 256];
__device__ float g_qkv[(size_t)NTOK * 768];
__device__ float g_att[NTOK * 256];
__device__ __nv_bfloat16 g_wtq_hi[768 * 256];   // W_qkv^T  [N][K]
__device__ __nv_bfloat16 g_wtq_lo[768 * 256];
__device__ __nv_bfloat16 g_wto_hi[256 * 256];   // W_o^T    [N][K]
__device__ __nv_bfloat16 g_wto_lo[256 * 256];

// ======================= helpers =======================
__device__ __forceinline__ uint32_t smem_u32(const void* p) {
    uint32_t a;
    asm("{ .reg .u64 t; cvta.to.shared.u64 t, %1; cvt.u32.u64 %0, t; }" : "=r"(a) : "l"(p));
    return a;
}
__device__ __forceinline__ void ldsm4(uint32_t r[4], uint32_t addr) {
    asm volatile("ldmatrix.sync.aligned.m8n8.x4.shared.b16 {%0,%1,%2,%3}, [%4];"
                 : "=r"(r[0]), "=r"(r[1]), "=r"(r[2]), "=r"(r[3]) : "r"(addr));
}
__device__ __forceinline__ void ldsm4t(uint32_t r[4], uint32_t addr) {
    asm volatile("ldmatrix.sync.aligned.m8n8.x4.trans.shared.b16 {%0,%1,%2,%3}, [%4];"
                 : "=r"(r[0]), "=r"(r[1]), "=r"(r[2]), "=r"(r[3]) : "r"(addr));
}
__device__ __forceinline__ void mma16816(float d[4], const uint32_t a[4],
                                         uint32_t b0, uint32_t b1) {
    asm volatile(
        "mma.sync.aligned.m16n8k16.row.col.f32.bf16.bf16.f32 "
        "{%0,%1,%2,%3}, {%4,%5,%6,%7}, {%8,%9}, {%0,%1,%2,%3};"
        : "+f"(d[0]), "+f"(d[1]), "+f"(d[2]), "+f"(d[3])
        : "r"(a[0]), "r"(a[1]), "r"(a[2]), "r"(a[3]), "r"(b0), "r"(b1));
}
// pack two fp32 -> bf16x2 (c0 in low half, c1 in high half)
__device__ __forceinline__ uint32_t pk(float c0, float c1) {
    uint32_t d;
    asm("cvt.rn.bf16x2.f32 %0, %1, %2;" : "=r"(d) : "f"(c1), "f"(c0));
    return d;
}
__device__ __forceinline__ float bf16rt(float v) {   // round-trip through bf16
    return __bfloat162float(__float2bfloat16(v));
}

// ======================= prep: W^T hi/lo split =======================
__global__ void prep_kernel(const float* __restrict__ wqkv, const float* __restrict__ wo) {
    int i = blockIdx.x * blockDim.x + threadIdx.x;
    if (i < 768 * 256) {
        int n = i >> 8, k = i & 255;
        float f = wqkv[k * 768 + n];
        __nv_bfloat16 h = __float2bfloat16(f);
        g_wtq_hi[i] = h;
        g_wtq_lo[i] = __float2bfloat16(f - __bfloat162float(h));
    } else if (i < 768 * 256 + 256 * 256) {
        int j = i - 768 * 256;
        int n = j >> 8, k = j & 255;
        float f = wo[k * 256 + n];
        __nv_bfloat16 h = __float2bfloat16(f);
        g_wto_hi[j] = h;
        g_wto_lo[j] = __float2bfloat16(f - __bfloat162float(h));
    }
}

// ======================= HMMA GEMM kernel (unchanged from R6) =======================
#define LDA      264
#define A_LO_OFF 67584
#define GB_OFF   135168
#define B_BUF    36864
#define B_HALF   18432
#define LDB_B    144
#define GS_SMEM  (GB_OFF + 2 * B_BUF)

__global__ __launch_bounds__(256, 1)
void gemm_hmma(const float* __restrict__ lin_in, const float* __restrict__ img_in,
               const __nv_bfloat16* __restrict__ wh, const __nv_bfloat16* __restrict__ wl,
               const float* __restrict__ bias,
               float* __restrict__ lin_out, float* __restrict__ img_out,
               int ntiles, int out_stride, int mode_in, int mode_out, int shifted)
{
    extern __shared__ char sb[];
    const uint32_t smb = smem_u32(sb);
    const int tid = threadIdx.x, wid = tid >> 5, lane = tid & 31;
    const int blk = blockIdx.x;
    const int sh = shifted ? 4 : 0;

    for (int g = tid; g < 4096; g += 256) {
        int t = g >> 5;
        int col0 = (g & 31) * 8;
        const float* sp;
        if (mode_in == 1) {
            int tok = blk * 128 + t;
            int m = tok >> 12, w = (tok >> 6) & 63, tt = tok & 63;
            int gh = ((w >> 3) * 8 + (tt >> 3) + sh) & 63;
            int gw = ((w & 7) * 8 + (tt & 7) + sh) & 63;
            sp = img_in + (size_t)((m * 64 + gh) * 64 + gw) * 256 + col0;
        } else {
            sp = lin_in + (size_t)(blk * 128 + t) * 256 + col0;
        }
        float4 f0 = *(const float4*)sp, f1 = *(const float4*)(sp + 4);
        float fv[8] = {f0.x, f0.y, f0.z, f0.w, f1.x, f1.y, f1.z, f1.w};
        uint32_t hw[4], lw[4];
#pragma unroll
        for (int q = 0; q < 4; ++q) {
            float h0 = bf16rt(fv[2 * q]), h1 = bf16rt(fv[2 * q + 1]);
            hw[q] = pk(h0, h1);
            lw[q] = pk(fv[2 * q] - h0, fv[2 * q + 1] - h1);
        }
        uint32_t off = ((uint32_t)t * LDA + col0) * 2;
        *(uint4*)(sb + off)            = make_uint4(hw[0], hw[1], hw[2], hw[3]);
        *(uint4*)(sb + A_LO_OFF + off) = make_uint4(lw[0], lw[1], lw[2], lw[3]);
    }

    const int mbase = (wid & 3) * 32;
    const int nbase = (wid >> 2) * 64;
    const int grp = lane >> 3, r8 = lane & 7;
    const int a_row = mbase + r8 + ((grp & 1) << 3);
    const int a_kof = (grp & 2) ? 8 : 0;
    const uint32_t aHi = smb + (uint32_t)(a_row * LDA + a_kof) * 2;
    const uint32_t aLo = aHi + A_LO_OFF;
    const int b_n  = r8 + ((grp & 2) << 2);
    const int b_kof = (grp & 1) ? 8 : 0;
    const uint32_t bBase = smb + GB_OFF + (uint32_t)((nbase + b_n) * 72 + b_kof) * 2;
    const int qr = lane >> 2, qc = (lane & 3) * 2;

    for (int nt = 0; nt < ntiles; ++nt) {
        float d[2][8][4];
#pragma unroll
        for (int mf = 0; mf < 2; ++mf)
#pragma unroll
            for (int nf = 0; nf < 8; ++nf)
#pragma unroll
                for (int q = 0; q < 4; ++q) d[mf][nf][q] = 0.f;

#pragma unroll
        for (int i = 0; i < 8; ++i) {
            int g = tid + i * 256;
            int half = g >> 10, j = g & 1023;
            int n = j >> 3, kq = j & 7;
            const __nv_bfloat16* W = half ? wl : wh;
            uint4 v = *(const uint4*)(W + (size_t)(nt * 128 + n) * 256 + kq * 8);
            *(uint4*)(sb + GB_OFF + half * B_HALF + n * LDB_B + kq * 16) = v;
        }
        __syncthreads();

        for (int c = 0; c < 4; ++c) {
            uint4 stg[8];
            if (c < 3) {
#pragma unroll
                for (int i = 0; i < 8; ++i) {
                    int g = tid + i * 256;
                    int half = g >> 10, j = g & 1023;
                    int n = j >> 3, kq = j & 7;
                    const __nv_bfloat16* W = half ? wl : wh;
                    stg[i] = *(const uint4*)(W + (size_t)(nt * 128 + n) * 256 + (c + 1) * 64 + kq * 8);
                }
            }
            const uint32_t bb0 = bBase + (uint32_t)(c & 1) * B_BUF;
#pragma unroll
            for (int kk8 = 0; kk8 < 4; ++kk8) {
                const int kg = c * 64 + kk8 * 16;
                uint32_t ah[2][4], al[2][4];
                ldsm4(ah[0], aHi + (uint32_t)kg * 2);
                ldsm4(ah[1], aHi + 16u * (LDA * 2) + (uint32_t)kg * 2);
                ldsm4(al[0], aLo + (uint32_t)kg * 2);
                ldsm4(al[1], aLo + 16u * (LDA * 2) + (uint32_t)kg * 2);
                uint32_t bh[4][4], bl[4][4];
                const uint32_t bb = bb0 + (uint32_t)kk8 * 32;
#pragma unroll
                for (int np = 0; np < 4; ++np) {
                    ldsm4(bh[np], bb + (uint32_t)np * (16 * LDB_B));
                    ldsm4(bl[np], bb + B_HALF + (uint32_t)np * (16 * LDB_B));
                }
#pragma unroll
                for (int mf = 0; mf < 2; ++mf)
#pragma unroll
                    for (int nf = 0; nf < 8; ++nf) {
                        const int np = nf >> 1, hv = (nf & 1) * 2;
                        mma16816(d[mf][nf], ah[mf], bh[np][hv], bh[np][hv + 1]);
                        mma16816(d[mf][nf], ah[mf], bl[np][hv], bl[np][hv + 1]);
                        mma16816(d[mf][nf], al[mf], bh[np][hv], bh[np][hv + 1]);
                    }
            }
            if (c < 3) {
#pragma unroll
                for (int i = 0; i < 8; ++i) {
                    int g = tid + i * 256;
                    int half = g >> 10, j = g & 1023;
                    int n = j >> 3, kq = j & 7;
                    *(uint4*)(sb + GB_OFF + ((c + 1) & 1) * B_BUF + half * B_HALF + n * LDB_B + kq * 16) = stg[i];
                }
            }
            __syncthreads();
        }

#pragma unroll
        for (int mf = 0; mf < 2; ++mf)
#pragma unroll
            for (int h8 = 0; h8 < 2; ++h8) {
                int row = mbase + mf * 16 + h8 * 8 + qr;
                int tok = blk * 128 + row;
                float* dst;
                if (mode_out == 0) {
                    dst = lin_out + (size_t)tok * out_stride + nt * 128;
                } else {
                    int m = tok >> 12, w = (tok >> 6) & 63, tt = tok & 63;
                    int gh = ((w >> 3) * 8 + (tt >> 3) + sh) & 63;
                    int gw = ((w & 7) * 8 + (tt & 7) + sh) & 63;
                    dst = img_out + (size_t)((m * 64 + gh) * 64 + gw) * 256 + nt * 128;
                }
#pragma unroll
                for (int nf = 0; nf < 8; ++nf) {
                    int col = nbase + nf * 8 + qc;
                    float b0 = bias[nt * 128 + col], b1 = bias[nt * 128 + col + 1];
                    *(float2*)(dst + col) = make_float2(d[mf][nf][h8 * 2] + b0,
                                                        d[mf][nf][h8 * 2 + 1] + b1);
                }
            }
    }
}

// ======================= HMMA flash attention kernel =======================
// One CTA = one window (64 tokens). 8 warps = 8 heads. No barriers after load.
// smem: Qh,Ql,Kh,Kl,Vh,Vl each [64][264] bf16 (33792 B) -> 202752 B total.
#define LDQ  264
#define AQH  0
#define AQL  33792
#define AKH  67584
#define AKL  101376
#define AVH  135168
#define AVL  168960
#define AT_SMEM 202752

__device__ __forceinline__ int regid(int wh, int ww, int t) {
    int r = t >> 3, c = t & 7;
    int hr = (wh == 7) ? ((r < 4) ? 1 : 2) : 0;
    int wr = (ww == 7) ? ((c < 4) ? 1 : 2) : 0;
    return hr * 3 + wr;
}

__global__ __launch_bounds__(256, 1)
void attn_hmma(int shifted)
{
    extern __shared__ char sb[];
    const uint32_t smb = smem_u32(sb);
    const int tid = threadIdx.x, wid = tid >> 5, lane = tid & 31;
    const int win = blockIdx.x;
    const int wh = (win & 63) >> 3, ww = win & 7;

    // ---- load 64x768 fp32 qkv, split hi/lo bf16 into smem ----
    {
        const int t = tid >> 2;
        const float* src = g_qkv + (size_t)(win * 64 + t) * 768;
#pragma unroll
        for (int i = 0; i < 24; ++i) {
            int col0 = ((tid & 3) + i * 4) * 8;      // 0..760
            float4 f0 = *(const float4*)(src + col0);
            float4 f1 = *(const float4*)(src + col0 + 4);
            float fv[8] = {f0.x, f0.y, f0.z, f0.w, f1.x, f1.y, f1.z, f1.w};
            uint32_t hw[4], lw[4];
#pragma unroll
            for (int q = 0; q < 4; ++q) {
                float h0 = bf16rt(fv[2 * q]), h1 = bf16rt(fv[2 * q + 1]);
                hw[q] = pk(h0, h1);
                lw[q] = pk(fv[2 * q] - h0, fv[2 * q + 1] - h1);
            }
            int sel = col0 >> 8, c = col0 & 255;
            uint32_t bh = (sel == 0) ? AQH : (sel == 1) ? AKH : AVH;
            uint32_t bl = (sel == 0) ? AQL : (sel == 1) ? AKL : AVL;
            uint32_t off = (uint32_t)(t * LDQ + c) * 2;
            *(uint4*)(sb + bh + off) = make_uint4(hw[0], hw[1], hw[2], hw[3]);
            *(uint4*)(sb + bl + off) = make_uint4(lw[0], lw[1], lw[2], lw[3]);
        }
    }
    __syncthreads();

    const int head = wid;
    const int hcol = head * 32;
    // lane decompositions
    const int arow = lane & 15, acolh = (lane >> 4) * 8;           // A ldsm
    const int grp = lane >> 3, r8 = lane & 7;
    const int b_n = r8 + ((grp & 2) << 2), b_k = (grp & 1) * 8;    // K (B) ldsm
    const int v_k = r8 + ((grp & 1) << 3), v_n = (grp & 2) << 2;   // V trans ldsm
    const int qr = lane >> 2, qc = (lane & 3) * 2;                 // C frag coords
    const float scale = 0.17677669529663687f;

    // col (key-token) region ids for this thread's 16 columns
    int creg[16];
#pragma unroll
    for (int j = 0; j < 8; ++j) {
        creg[2 * j]     = regid(wh, ww, j * 8 + qc);
        creg[2 * j + 1] = regid(wh, ww, j * 8 + qc + 1);
    }

    for (int mh = 0; mh < 2; ++mh) {
        const int rbase = mh * 32;
        // ---- Q fragments ----
        uint32_t qh[2][2][4], ql[2][2][4];
#pragma unroll
        for (int i = 0; i < 2; ++i)
#pragma unroll
            for (int kt = 0; kt < 2; ++kt) {
                uint32_t off = (uint32_t)((rbase + i * 16 + arow) * LDQ + hcol + kt * 16 + acolh) * 2;
                ldsm4(qh[i][kt], smb + AQH + off);
                ldsm4(ql[i][kt], smb + AQL + off);
            }

        // ---- S = Q K^T (3-term split) ----
        float s[2][8][4];
#pragma unroll
        for (int i = 0; i < 2; ++i)
#pragma unroll
            for (int j = 0; j < 8; ++j)
#pragma unroll
                for (int q = 0; q < 4; ++q) s[i][j][q] = 0.f;
#pragma unroll
        for (int kt = 0; kt < 2; ++kt)
#pragma unroll
            for (int ng = 0; ng < 4; ++ng) {
                uint32_t kh4[4], kl4[4];
                uint32_t ka = (uint32_t)((ng * 16 + b_n) * LDQ + hcol + kt * 16 + b_k) * 2;
                ldsm4(kh4, smb + AKH + ka);
                ldsm4(kl4, smb + AKL + ka);
#pragma unroll
                for (int i = 0; i < 2; ++i) {
                    mma16816(s[i][2 * ng],     qh[i][kt], kh4[0], kh4[1]);
                    mma16816(s[i][2 * ng],     qh[i][kt], kl4[0], kl4[1]);
                    mma16816(s[i][2 * ng],     ql[i][kt], kh4[0], kh4[1]);
                    mma16816(s[i][2 * ng + 1], qh[i][kt], kh4[2], kh4[3]);
                    mma16816(s[i][2 * ng + 1], qh[i][kt], kl4[2], kl4[3]);
                    mma16816(s[i][2 * ng + 1], ql[i][kt], kh4[2], kh4[3]);
                }
            }

        // ---- scale + swin mask + softmax (register/quad-shuffle) ----
#pragma unroll
        for (int i = 0; i < 2; ++i) {
            int rr0 = regid(wh, ww, rbase + i * 16 + qr);
            int rr1 = regid(wh, ww, rbase + i * 16 + qr + 8);
#pragma unroll
            for (int j = 0; j < 8; ++j) {
                s[i][j][0] = s[i][j][0] * scale;
                s[i][j][1] = s[i][j][1] * scale;
                s[i][j][2] = s[i][j][2] * scale;
                s[i][j][3] = s[i][j][3] * scale;
                if (shifted) {
                    if (creg[2 * j]     != rr0) s[i][j][0] += -1e9f;
                    if (creg[2 * j + 1] != rr0) s[i][j][1] += -1e9f;
                    if (creg[2 * j]     != rr1) s[i][j][2] += -1e9f;
                    if (creg[2 * j + 1] != rr1) s[i][j][3] += -1e9f;
                }
            }
            float m0 = -3.4e38f, m1 = -3.4e38f;
#pragma unroll
            for (int j = 0; j < 8; ++j) {
                m0 = fmaxf(m0, fmaxf(s[i][j][0], s[i][j][1]));
                m1 = fmaxf(m1, fmaxf(s[i][j][2], s[i][j][3]));
            }
            m0 = fmaxf(m0, __shfl_xor_sync(0xffffffffu, m0, 1));
            m0 = fmaxf(m0, __shfl_xor_sync(0xffffffffu, m0, 2));
            m1 = fmaxf(m1, __shfl_xor_sync(0xffffffffu, m1, 1));
            m1 = fmaxf(m1, __shfl_xor_sync(0xffffffffu, m1, 2));
            float s0 = 0.f, s1 = 0.f;
#pragma unroll
            for (int j = 0; j < 8; ++j) {
                s[i][j][0] = __expf(s[i][j][0] - m0); s0 += s[i][j][0];
                s[i][j][1] = __expf(s[i][j][1] - m0); s0 += s[i][j][1];
                s[i][j][2] = __expf(s[i][j][2] - m1); s1 += s[i][j][2];
                s[i][j][3] = __expf(s[i][j][3] - m1); s1 += s[i][j][3];
            }
            s0 += __shfl_xor_sync(0xffffffffu, s0, 1);
            s0 += __shfl_xor_sync(0xffffffffu, s0, 2);
            s1 += __shfl_xor_sync(0xffffffffu, s1, 1);
            s1 += __shfl_xor_sync(0xffffffffu, s1, 2);
            float i0 = 1.f / s0, i1 = 1.f / s1;
#pragma unroll
            for (int j = 0; j < 8; ++j) {
                s[i][j][0] *= i0; s[i][j][1] *= i0;
                s[i][j][2] *= i1; s[i][j][3] *= i1;
            }
        }

        // ---- pack P into A-fragments (hi/lo split); C-frag layout == A-frag ----
        uint32_t ph[2][4][4], pl[2][4][4];
#pragma unroll
        for (int i = 0; i < 2; ++i)
#pragma unroll
            for (int kt = 0; kt < 4; ++kt) {
                const float* e = s[i][2 * kt];
                const float* o2 = s[i][2 * kt + 1];
                float h;
                h = bf16rt(e[0]);  float h2 = bf16rt(e[1]);
                ph[i][kt][0] = pk(h, h2);  pl[i][kt][0] = pk(e[0] - h, e[1] - h2);
                h = bf16rt(e[2]);  h2 = bf16rt(e[3]);
                ph[i][kt][1] = pk(h, h2);  pl[i][kt][1] = pk(e[2] - h, e[3] - h2);
                h = bf16rt(o2[0]); h2 = bf16rt(o2[1]);
                ph[i][kt][2] = pk(h, h2);  pl[i][kt][2] = pk(o2[0] - h, o2[1] - h2);
                h = bf16rt(o2[2]); h2 = bf16rt(o2[3]);
                ph[i][kt][3] = pk(h, h2);  pl[i][kt][3] = pk(o2[2] - h, o2[3] - h2);
            }

        // ---- O = P V (V via ldmatrix.trans, 3-term split) ----
        float o[2][4][4];
#pragma unroll
        for (int i = 0; i < 2; ++i)
#pragma unroll
            for (int nt = 0; nt < 4; ++nt)
#pragma unroll
                for (int q = 0; q < 4; ++q) o[i][nt][q] = 0.f;
#pragma unroll
        for (int kt = 0; kt < 4; ++kt)
#pragma unroll
            for (int ng = 0; ng < 2; ++ng) {
                uint32_t vh4[4], vl4[4];
                uint32_t va = (uint32_t)((kt * 16 + v_k) * LDQ + hcol + ng * 16 + v_n) * 2;
                ldsm4t(vh4, smb + AVH + va);
                ldsm4t(vl4, smb + AVL + va);
#pragma unroll
                for (int i = 0; i < 2; ++i) {
                    mma16816(o[i][2 * ng],     ph[i][kt], vh4[0], vh4[1]);
                    mma16816(o[i][2 * ng],     ph[i][kt], vl4[0], vl4[1]);
                    mma16816(o[i][2 * ng],     pl[i][kt], vh4[0], vh4[1]);
                    mma16816(o[i][2 * ng + 1], ph[i][kt], vh4[2], vh4[3]);
                    mma16816(o[i][2 * ng + 1], ph[i][kt], vl4[2], vl4[3]);
                    mma16816(o[i][2 * ng + 1], pl[i][kt], vh4[2], vh4[3]);
                }
            }

        // ---- store O tiles to g_att ----
#pragma unroll
        for (int i = 0; i < 2; ++i) {
            int row = win * 64 + rbase + i * 16 + qr;
#pragma unroll
            for (int nt = 0; nt < 4; ++nt) {
                int col = hcol + nt * 8 + qc;
                *(float2*)(g_att + (size_t)row * 256 + col) =
                    make_float2(o[i][nt][0], o[i][nt][1]);
                *(float2*)(g_att + (size_t)(row + 8) * 256 + col) =
                    make_float2(o[i][nt][2], o[i][nt][3]);
            }
        }
    }
}

// ======================= launch =======================
extern "C" void kernel_launch(void* const* d_in, const int* in_sizes, int n_in,
                              void* d_out, int out_size) {
    (void)in_sizes; (void)n_in; (void)out_size;
    const float* x    = (const float*)d_in[0];
    const float* wqkv = (const float*)d_in[1];
    const float* bqkv = (const float*)d_in[2];
    const float* wo   = (const float*)d_in[3];
    const float* bo   = (const float*)d_in[4];
    float* out = (float*)d_out;

    cudaFuncSetAttribute(gemm_hmma, cudaFuncAttributeMaxDynamicSharedMemorySize, GS_SMEM);
    cudaFuncSetAttribute(attn_hmma, cudaFuncAttributeMaxDynamicSharedMemorySize, AT_SMEM);

    float* ypass1; cudaGetSymbolAddress((void**)&ypass1, g_y);
    __nv_bfloat16 *wqh, *wql, *woh, *wol;
    cudaGetSymbolAddress((void**)&wqh, g_wtq_hi);
    cudaGetSymbolAddress((void**)&wql, g_wtq_lo);
    cudaGetSymbolAddress((void**)&woh, g_wto_hi);
    cudaGetSymbolAddress((void**)&wol, g_wto_lo);
    float *qkvp, *attp;
    cudaGetSymbolAddress((void**)&qkvp, g_qkv);
    cudaGetSymbolAddress((void**)&attp, g_att);

    prep_kernel<<<1024, 256>>>(wqkv, wo);

    for (int pass = 0; pass < 2; ++pass) {
        const float* img = pass ? (const float*)ypass1 : x;
        float* oimg = pass ? out : ypass1;
        gemm_hmma<<<1024, 256, GS_SMEM>>>(nullptr, img, wqh, wql, bqkv,
                                          qkvp, nullptr, 6, 768, 1, 0, pass);
        attn_hmma<<<2048, 256, AT_SMEM>>>(pass);
        gemm_hmma<<<1024, 256, GS_SMEM>>>(attp, nullptr, woh, wol, bo,
                                          nullptr, oimg, 2, 256, 0, 1, pass);
    }
}